// round 15
// baseline (speedup 1.0000x reference)
#include <cuda_runtime.h>
#include <cstdint>

#define NB 2
#define NPTS 8192
#define CH 128
#define KNN 16
#define NGRP 8
#define CPG 16
#define NK (NPTS*KNN)
#define TS 132          /* pre SIMT gemm f32 stride */
#define WST 132         /* bgemm W smem stride */
#define XT2 68          /* qkv/post X tile stride */
typedef unsigned long long u64;

// ---------------- scratch ----------------------------------------------------
__device__ float  g_nf [NB*CH*NPTS];                 // (B,C,N)
__device__ float  g_q  [NB*NPTS*CH];                 // (B,N,C)  aq = att1*q
__device__ float  g_kf [NB*NPTS*CH];                 // (B,N,C)  ak = att1*k
__device__ float  g_vf [NB*NPTS*CH];                 // (B,N,C)  v
__device__ int    g_idx[NB*NPTS*KNN];                // (B,N,K) == (B,NK)
__device__ float  g_bufA[(size_t)NB*NK*CH];          // (B,NK,C) att_pre
__device__ float  g_o  [NB*CH*NPTS];                 // (B,C,N) softmaxV + residual
__device__ float  g_y  [NB*CH*NPTS];                 // (B,C,N) pre-norm post out
__device__ float  g_wt [2*16384];                    // k-major: [0]=M, [1]=att2
__device__ float  g_wqc[16384];                      // row-major att1*wq
__device__ float  g_wkc[16384];                      // row-major att1*wk
__device__ float  g_cb [128];                        // att1*pos2_b + att1_b
__device__ float  g_bqc[128];                        // att1*wq_b
__device__ float  g_bkc[128];                        // att1*wk_b
__device__ double g_relmom[NB][9];                   // zero-init; re-zeroed at end
__device__ double g_statsA[NB][NGRP][2];
__device__ double g_statsP[NB][NGRP][2];

__global__ void zero_stats_kernel() {
    int t = threadIdx.x;
    if (t < NB*9)        ((double*)g_relmom)[t] = 0.0;
    if (t < NB*NGRP*2) { ((double*)g_statsA)[t] = 0.0; ((double*)g_statsP)[t] = 0.0; }
}

// ---------------- weight composition -----------------------------------------
// z=0: M = att1*pos2  -> g_wt[0] k-major
// z=1: att1*wq        -> g_wqc row-major
// z=2: att1*wk        -> g_wkc row-major
__global__ __launch_bounds__(256) void compose_kernel(
        const float* __restrict__ att1_w, const float* __restrict__ pos2_w,
        const float* __restrict__ wq_w,  const float* __restrict__ wk_w) {
    const int z = blockIdx.y;
    int e = blockIdx.x * 256 + threadIdx.x;     // 16384 per z
    int i = e >> 7, j = e & 127;
    const float* B = (z == 0) ? pos2_w : (z == 1) ? wq_w : wk_w;
    const float* arow = att1_w + i * 128;
    float s = 0.f;
    #pragma unroll 4
    for (int c = 0; c < 128; c++) s = fmaf(__ldg(arow + c), __ldg(B + c*128 + j), s);
    if (z == 0) g_wt[j*128 + i] = s;
    else if (z == 1) g_wqc[e] = s;
    else g_wkc[e] = s;
}
// att2 transpose to k-major + composed biases
__global__ __launch_bounds__(512) void prep2_kernel(
        const float* __restrict__ att2_w, const float* __restrict__ att1_w,
        const float* __restrict__ pos2_b, const float* __restrict__ att1_b,
        const float* __restrict__ wq_b,  const float* __restrict__ wk_b) {
    int tid = blockIdx.x * 512 + threadIdx.x;
    if (tid < 16384) {
        int o = tid >> 7, k = tid & 127;
        g_wt[16384 + k*128 + o] = att2_w[tid];
    }
    if (blockIdx.x == 0 && threadIdx.x < 384) {
        int z = threadIdx.x >> 7, i = threadIdx.x & 127;
        const float* bb = (z == 0) ? pos2_b : (z == 1) ? wq_b : wk_b;
        const float* arow = att1_w + i * 128;
        float s = 0.f;
        #pragma unroll 4
        for (int c = 0; c < 128; c++) s = fmaf(arow[c], bb[c], s);
        if (z == 0) g_cb[i] = s + att1_b[i];
        else if (z == 1) g_bqc[i] = s;
        else g_bkc[i] = s;
    }
}

// ---------------- f32x2 helpers ----------------------------------------------
__device__ __forceinline__ u64 pack2s(float x) {
    u64 r; asm("mov.b64 %0, {%1,%2};" : "=l"(r) : "f"(x), "f"(x)); return r;
}
__device__ __forceinline__ u64 ffma2(u64 a, u64 b, u64 c) {
    u64 d; asm("fma.rn.f32x2 %0, %1, %2, %3;" : "=l"(d) : "l"(a), "l"(b), "l"(c));
    return d;
}
__device__ __forceinline__ float2 unpk(u64 v) {
    float2 f; asm("mov.b64 {%0,%1}, %2;" : "=f"(f.x), "=f"(f.y) : "l"(v)); return f;
}
__device__ __forceinline__ float warp_sum(float v) {
    #pragma unroll
    for (int o = 16; o > 0; o >>= 1) v += __shfl_down_sync(0xffffffffu, v, o);
    return v;
}

// ---------------- KNN + rel moments ------------------------------------------
__global__ __launch_bounds__(128) void knn_kernel(const float* __restrict__ xyz) {
    const int b = blockIdx.y;
    const int q = blockIdx.x * 128 + threadIdx.x;
    const float* X = xyz + b * 3 * NPTS;
    const float qx = X[q], qy = X[q + NPTS], qz = X[q + 2*NPTS];
    const float c0 = -2.f*qx, c1 = -2.f*qy, c2 = -2.f*qz;
    float nd[KNN]; int ni[KNN];
    #pragma unroll
    for (int i = 0; i < KNN; i++) { nd[i] = 3.4e38f; ni[i] = 0; }
    float worst = 3.4e38f;
    __shared__ float4 tile[256];
    for (int t0 = 0; t0 < NPTS; t0 += 256) {
        __syncthreads();
        for (int j = threadIdx.x; j < 256; j += 128) {
            int jj = t0 + j;
            float x = X[jj], y = X[jj + NPTS], z = X[jj + 2*NPTS];
            tile[j] = make_float4(x, y, z, x*x + y*y + z*z);
        }
        __syncthreads();
        #pragma unroll 4
        for (int j = 0; j < 256; j++) {
            float4 c = tile[j];
            float d = fmaf(c0, c.x, fmaf(c1, c.y, fmaf(c2, c.z, c.w)));
            if (d < worst) {
                int pos = 15;
                #pragma unroll 1
                while (pos > 0 && nd[pos-1] > d) {
                    nd[pos] = nd[pos-1]; ni[pos] = ni[pos-1]; --pos;
                }
                nd[pos] = d; ni[pos] = t0 + j;
                worst = nd[15];
            }
        }
    }
    const int base = (b * NPTS + q) * KNN;
    float mom[9];
    #pragma unroll
    for (int m = 0; m < 9; m++) mom[m] = 0.f;
    #pragma unroll
    for (int i = 0; i < KNN; i++) {
        int j = ni[i];
        g_idx[base + i] = j;
        float dx = X[j] - qx, dy = X[j + NPTS] - qy, dz = X[j + 2*NPTS] - qz;
        mom[0] += dx; mom[1] += dy; mom[2] += dz;
        mom[3] += dx*dx; mom[4] += dx*dy; mom[5] += dx*dz;
        mom[6] += dy*dy; mom[7] += dy*dz; mom[8] += dz*dz;
    }
    int lane = threadIdx.x & 31;
    #pragma unroll
    for (int m = 0; m < 9; m++) {
        float s = warp_sum(mom[m]);
        if (lane == 0) atomicAdd(&g_relmom[b][m], (double)s);
    }
}

// ---------------- SIMT GEMM: pre (Cin=64), occ 2 ------------------------------
__global__ __launch_bounds__(256, 2) void pre_kernel(
        const float* __restrict__ W, const float* __restrict__ bias,
        const float* __restrict__ Xin) {
    const int b  = blockIdx.y;
    const int n0 = blockIdx.x * 128;
    extern __shared__ float sm[];
    float* Ws = sm;
    float* Xs = sm + 64 * TS;
    const int tid = threadIdx.x;
    for (int e = tid; e < CH * 64; e += 256) {
        int m = e >> 6, k = e & 63;
        Ws[k * TS + m] = W[e];
    }
    const float* Xp = Xin + (size_t)b * 64 * NPTS + n0;
    for (int e = tid; e < 64 * 128; e += 256) {
        int k = e >> 7, c = e & 127;
        Xs[k * TS + c] = Xp[(size_t)k * NPTS + c];
    }
    __syncthreads();
    const int ty = tid >> 4, tx = tid & 15;
    float acc[8][8];
    #pragma unroll
    for (int i = 0; i < 8; i++)
        #pragma unroll
        for (int j = 0; j < 8; j++) acc[i][j] = 0.f;
    #pragma unroll 2
    for (int k = 0; k < 64; k++) {
        float4 w0 = *(const float4*)(Ws + k*TS + ty*8);
        float4 w1 = *(const float4*)(Ws + k*TS + ty*8 + 4);
        float4 x0 = *(const float4*)(Xs + k*TS + tx*8);
        float4 x1 = *(const float4*)(Xs + k*TS + tx*8 + 4);
        float wf[8] = {w0.x,w0.y,w0.z,w0.w,w1.x,w1.y,w1.z,w1.w};
        float xf[8] = {x0.x,x0.y,x0.z,x0.w,x1.x,x1.y,x1.z,x1.w};
        #pragma unroll
        for (int i = 0; i < 8; i++)
            #pragma unroll
            for (int j = 0; j < 8; j++)
                acc[i][j] = fmaf(wf[i], xf[j], acc[i][j]);
    }
    #pragma unroll
    for (int i = 0; i < 8; i++) {
        int r = ty*8 + i;
        float bf = bias[r];
        float* yp = g_nf + ((size_t)b * CH + r) * NPTS + n0 + tx*8;
        float4 o0 = {acc[i][0]+bf, acc[i][1]+bf, acc[i][2]+bf, acc[i][3]+bf};
        float4 o1 = {acc[i][4]+bf, acc[i][5]+bf, acc[i][6]+bf, acc[i][7]+bf};
        *(float4*)yp = o0; *(float4*)(yp+4) = o1;
    }
}

// ---------------- fused aq/ak/v GEMM (64 cols, occ 2) -------------------------
#define QKV_SMEM ((128*TS + 128*XT2) * 4)
__global__ __launch_bounds__(256, 2) void qkv_kernel(
        const float* __restrict__ wq, const float* __restrict__ bq,
        const float* __restrict__ wk, const float* __restrict__ bk,
        const float* __restrict__ wv, const float* __restrict__ bv) {
    const int b  = blockIdx.y;
    const int n0 = blockIdx.x * 64;
    const int z  = blockIdx.z;
    const float* W    = (z == 0) ? wq : (z == 1) ? wk : wv;
    const float* bias = (z == 0) ? bq : (z == 1) ? bk : bv;
    float* Y = (z == 0) ? g_q : (z == 1) ? g_kf : g_vf;
    extern __shared__ float sm[];
    float* Ws = sm;
    float* Xs = sm + 128 * TS;
    const int tid = threadIdx.x;
    for (int e = tid; e < CH * 128; e += 256) {
        int m = e >> 7, k = e & 127;
        Ws[k * TS + m] = W[e];
    }
    const float* Xp = g_nf + (size_t)b * CH * NPTS + n0;
    for (int e = tid; e < 128 * 64; e += 256) {
        int k = e >> 6, c = e & 63;
        Xs[k * XT2 + c] = Xp[(size_t)k * NPTS + c];
    }
    __syncthreads();
    const int ty = tid >> 4, tx = tid & 15;
    float acc[8][4];
    #pragma unroll
    for (int i = 0; i < 8; i++)
        #pragma unroll
        for (int j = 0; j < 4; j++) acc[i][j] = 0.f;
    #pragma unroll 4
    for (int k = 0; k < 128; k++) {
        float4 w0 = *(const float4*)(Ws + k*TS + ty*8);
        float4 w1 = *(const float4*)(Ws + k*TS + ty*8 + 4);
        float4 x0 = *(const float4*)(Xs + k*XT2 + tx*4);
        float wf[8] = {w0.x,w0.y,w0.z,w0.w,w1.x,w1.y,w1.z,w1.w};
        float xf[4] = {x0.x,x0.y,x0.z,x0.w};
        #pragma unroll
        for (int i = 0; i < 8; i++)
            #pragma unroll
            for (int j = 0; j < 4; j++)
                acc[i][j] = fmaf(wf[i], xf[j], acc[i][j]);
    }
    float bf[8];
    #pragma unroll
    for (int i = 0; i < 8; i++) bf[i] = bias[ty*8 + i];
    #pragma unroll
    for (int j = 0; j < 4; j++) {
        int c = n0 + tx*4 + j;
        float* yp = Y + ((size_t)b * NPTS + c) * CH + ty*8;
        float4 o0 = {acc[0][j]+bf[0], acc[1][j]+bf[1], acc[2][j]+bf[2], acc[3][j]+bf[3]};
        float4 o1 = {acc[4][j]+bf[4], acc[5][j]+bf[5], acc[6][j]+bf[6], acc[7][j]+bf[7]};
        *(float4*)yp = o0; *(float4*)(yp+4) = o1;
    }
}

// ---------------- big streaming GEMM -----------------------------------------
// MODE 1: X generated from rel (pos1+GN+lrelu); out = M*X1 + cb + aq - ak,
//         + statsA -> bufA
// MODE 3: X gn+lrelu on load; epilogue = softmax*V + residual -> g_o
#define BG_SMEM ((128*WST + 2*16*WST + 1536) * 4)
template<int MODE>
__global__ __launch_bounds__(256, 2) void bgemm_kernel(
        const float* __restrict__ Wg, const float* __restrict__ bias,
        const float* __restrict__ Xin, float* __restrict__ Out,
        const float* __restrict__ gnw, const float* __restrict__ gnb,
        const float* __restrict__ xyz,
        const float* __restrict__ p1w, const float* __restrict__ p1b) {
    const int b  = blockIdx.y;
    const int cb = blockIdx.x * 128;
    extern __shared__ float sm[];
    float* Ws   = sm;                       // [128][WST]; later C staging [ch][129]
    float* Xb0  = sm + 128*WST;             // [16][WST]
    float* Xb1  = Xb0 + 16*WST;
    float* misc = Xb1 + 16*WST;
    float* s_bias = misc;                   // 128
    int*   s_idx  = (int*)(misc + 128);     // 128
    float* s_m    = misc + 256;             // 8
    float* s_r    = misc + 264;             // 8
    float* s_red  = misc + 272;             // 16
    float* s_wA   = misc + 288;             // 384 (MODE1)
    float* s_c0   = misc + 672;             // 128 (MODE1)
    float* s_rx   = misc + 800;             // 128 (MODE1)
    float* s_ry   = misc + 928;             // 128
    float* s_rz   = misc + 1056;            // 128
    float* s_ga   = misc + 1184;            // 128 (MODE3)
    float* s_be   = misc + 1312;            // 128 (MODE3)
    const int tid = threadIdx.x;
    const int lane = tid & 31;
    const int r0 = (tid >> 5) * 16;
    const int c0 = lane * 2;

    if (tid < 128) s_bias[tid] = bias[tid];
    if (tid < 128) s_idx[tid] = g_idx[b*NK + cb + tid];
    if (MODE == 1 && tid < 16) s_red[tid] = 0.f;
    if (MODE == 1) {
        if (tid < 128) {
            const float* X = xyz + b * 3 * NPTS;
            int j = g_idx[b*NK + cb + tid];
            int n = (cb >> 4) + (tid >> 4);
            s_rx[tid] = X[j]          - X[n];
            s_ry[tid] = X[j + NPTS]   - X[n + NPTS];
            s_rz[tid] = X[j + 2*NPTS] - X[n + 2*NPTS];
        }
        if (tid < 8) {   // closed-form pos1 GN stats from rel moments
            double R0 = g_relmom[b][0], R1 = g_relmom[b][1], R2 = g_relmom[b][2];
            double S00 = g_relmom[b][3], S01 = g_relmom[b][4], S02 = g_relmom[b][5];
            double S11 = g_relmom[b][6], S12 = g_relmom[b][7], S22 = g_relmom[b][8];
            double su = 0.0, sq = 0.0;
            for (int o = tid*16; o < tid*16 + 16; o++) {
                double w0 = p1w[o*3], w1 = p1w[o*3+1], w2 = p1w[o*3+2];
                double bb = p1b[o];
                double wr = w0*R0 + w1*R1 + w2*R2;
                su += wr + (double)NK * bb;
                double wsw = w0*w0*S00 + w1*w1*S11 + w2*w2*S22
                           + 2.0*(w0*w1*S01 + w0*w2*S02 + w1*w2*S12);
                sq += wsw + 2.0*bb*wr + (double)NK*bb*bb;
            }
            double cnt  = 16.0 * (double)NK;
            double mean = su / cnt;
            double var  = sq / cnt - mean*mean;
            s_m[tid] = (float)mean;
            s_r[tid] = (float)(1.0 / sqrt(var + 1e-5));
        }
    }
    if (MODE == 3) {
        if (tid < 128) { s_ga[tid] = gnw[tid]; s_be[tid] = gnb[tid]; }
        if (tid < 8) {
            double cnt = (double)CPG * (double)NK;
            double su = g_statsA[b][tid][0], sq = g_statsA[b][tid][1];
            double mean = su / cnt;
            double var  = sq / cnt - mean*mean;
            s_m[tid] = (float)mean;
            s_r[tid] = (float)(1.0 / sqrt(var + 1e-5));
        }
    }
    // W -> smem k-major
    for (int e = tid; e < 16384; e += 256) Ws[(e >> 7)*WST + (e & 127)] = Wg[e];
    if (MODE == 1) {
        __syncthreads();     // stats ready
        if (tid < 128) {     // folded GN constants
            float sc = s_r[tid >> 4] * gnw[tid];
            s_wA[tid*3+0] = p1w[tid*3+0] * sc;
            s_wA[tid*3+1] = p1w[tid*3+1] * sc;
            s_wA[tid*3+2] = p1w[tid*3+2] * sc;
            s_c0[tid] = (p1b[tid] - s_m[tid >> 4]) * sc + gnb[tid];
        }
    }
    __syncthreads();

    const int lcol = tid >> 1, lseg = tid & 1;
    const float* xsrc = (MODE == 1) ? nullptr
                      : Xin + ((size_t)b*NK + cb + lcol)*CH + lseg*8;
    const float rx = (MODE == 1) ? s_rx[lcol] : 0.f;
    const float ry = (MODE == 1) ? s_ry[lcol] : 0.f;
    const float rz = (MODE == 1) ? s_rz[lcol] : 0.f;

    // produce chunk 0
    {
        float v8[8];
        #pragma unroll
        for (int i = 0; i < 8; i++) {
            if (MODE == 1) {
                int ch = lseg*8 + i;
                float t = fmaf(s_wA[ch*3], rx, fmaf(s_wA[ch*3+1], ry,
                          fmaf(s_wA[ch*3+2], rz, s_c0[ch])));
                v8[i] = t >= 0.f ? t : 0.1f*t;
            }
        }
        if (MODE != 1) {
            float4 pa = *(const float4*)(xsrc);
            float4 pb = *(const float4*)(xsrc + 4);
            #pragma unroll
            for (int i = 0; i < 8; i++)
                v8[i] = (i < 4) ? (&pa.x)[i] : (&pb.x)[i-4];
            #pragma unroll
            for (int i = 0; i < 8; i++) {
                int ch = lseg*8 + i;
                float t = fmaf((v8[i] - s_m[ch>>4]) * s_r[ch>>4], s_ga[ch], s_be[ch]);
                v8[i] = t >= 0.f ? t : 0.1f*t;
            }
        }
        #pragma unroll
        for (int i = 0; i < 8; i++) Xb0[(lseg*8+i)*WST + lcol] = v8[i];
    }
    __syncthreads();

    u64 acc[8][4];
    #pragma unroll
    for (int m = 0; m < 8; m++)
        #pragma unroll
        for (int j = 0; j < 4; j++) acc[m][j] = 0ull;

    #pragma unroll 1
    for (int c = 0; c < 8; c++) {
        float v8[8];
        if (c < 7) {
            if (MODE == 1) {
                #pragma unroll
                for (int i = 0; i < 8; i++) {
                    int ch = (c+1)*16 + lseg*8 + i;
                    float t = fmaf(s_wA[ch*3], rx, fmaf(s_wA[ch*3+1], ry,
                              fmaf(s_wA[ch*3+2], rz, s_c0[ch])));
                    v8[i] = t >= 0.f ? t : 0.1f*t;
                }
            } else {
                const float* src = xsrc + (c+1)*16;
                float4 pa = *(const float4*)(src);
                float4 pb = *(const float4*)(src + 4);
                #pragma unroll
                for (int i = 0; i < 8; i++)
                    v8[i] = (i < 4) ? (&pa.x)[i] : (&pb.x)[i-4];
                #pragma unroll
                for (int i = 0; i < 8; i++) {
                    int ch = (c+1)*16 + lseg*8 + i;
                    float t = fmaf((v8[i] - s_m[ch>>4]) * s_r[ch>>4], s_ga[ch], s_be[ch]);
                    v8[i] = t >= 0.f ? t : 0.1f*t;
                }
            }
        }
        const float* Wc = Ws + c*16*WST;
        const float* Xc = (c & 1) ? Xb1 : Xb0;
        #pragma unroll
        for (int kk = 0; kk < 16; kk++) {
            const ulonglong2* wp = (const ulonglong2*)(Wc + kk*WST + r0);
            ulonglong2 wA = wp[0], wB = wp[1], wC = wp[2], wD = wp[3];
            const float* xp = Xc + kk*WST + c0;
            u64 xa = *(const u64*)xp, xbv = *(const u64*)(xp + 64);
            float2 fa = unpk(xa), fb = unpk(xbv);
            u64 x0 = pack2s(fa.x), x1 = pack2s(fa.y);
            u64 x2 = pack2s(fb.x), x3 = pack2s(fb.y);
            acc[0][0]=ffma2(wA.x,x0,acc[0][0]); acc[0][1]=ffma2(wA.x,x1,acc[0][1]);
            acc[0][2]=ffma2(wA.x,x2,acc[0][2]); acc[0][3]=ffma2(wA.x,x3,acc[0][3]);
            acc[1][0]=ffma2(wA.y,x0,acc[1][0]); acc[1][1]=ffma2(wA.y,x1,acc[1][1]);
            acc[1][2]=ffma2(wA.y,x2,acc[1][2]); acc[1][3]=ffma2(wA.y,x3,acc[1][3]);
            acc[2][0]=ffma2(wB.x,x0,acc[2][0]); acc[2][1]=ffma2(wB.x,x1,acc[2][1]);
            acc[2][2]=ffma2(wB.x,x2,acc[2][2]); acc[2][3]=ffma2(wB.x,x3,acc[2][3]);
            acc[3][0]=ffma2(wB.y,x0,acc[3][0]); acc[3][1]=ffma2(wB.y,x1,acc[3][1]);
            acc[3][2]=ffma2(wB.y,x2,acc[3][2]); acc[3][3]=ffma2(wB.y,x3,acc[3][3]);
            acc[4][0]=ffma2(wC.x,x0,acc[4][0]); acc[4][1]=ffma2(wC.x,x1,acc[4][1]);
            acc[4][2]=ffma2(wC.x,x2,acc[4][2]); acc[4][3]=ffma2(wC.x,x3,acc[4][3]);
            acc[5][0]=ffma2(wC.y,x0,acc[5][0]); acc[5][1]=ffma2(wC.y,x1,acc[5][1]);
            acc[5][2]=ffma2(wC.y,x2,acc[5][2]); acc[5][3]=ffma2(wC.y,x3,acc[5][3]);
            acc[6][0]=ffma2(wD.x,x0,acc[6][0]); acc[6][1]=ffma2(wD.x,x1,acc[6][1]);
            acc[6][2]=ffma2(wD.x,x2,acc[6][2]); acc[6][3]=ffma2(wD.x,x3,acc[6][3]);
            acc[7][0]=ffma2(wD.y,x0,acc[7][0]); acc[7][1]=ffma2(wD.y,x1,acc[7][1]);
            acc[7][2]=ffma2(wD.y,x2,acc[7][2]); acc[7][3]=ffma2(wD.y,x3,acc[7][3]);
        }
        if (c < 7) {
            float* Xn = (c & 1) ? Xb0 : Xb1;
            #pragma unroll
            for (int i = 0; i < 8; i++) Xn[(lseg*8+i)*WST + lcol] = v8[i];
        }
        __syncthreads();
    }

    // stage C into Ws region [ch][col] at stride 129 (conflict-free reads)
    #pragma unroll
    for (int mp = 0; mp < 8; mp++) {
        int r = r0 + 2*mp;
        #pragma unroll
        for (int j = 0; j < 4; j++) {
            int col = c0 + (j & 1) + 64*(j >> 1);
            float2 d = unpk(acc[mp][j]);
            Ws[r*129 + col]     = d.x;
            Ws[(r+1)*129 + col] = d.y;
        }
    }
    __syncthreads();

    const int ch = tid & 127;
    const float bv = s_bias[ch];
    if (MODE == 3) {
        // softmax over K=16 per point (block holds 8 complete points) + V + res
        const int half = tid >> 7;
        float o4[4];
        #pragma unroll
        for (int p = 0; p < 4; p++) {
            int colb = (half*4 + p) * 16;
            float s = 0.f, a = 0.f;
            #pragma unroll
            for (int k = 0; k < 16; k++) {
                float e = __expf(Ws[ch*129 + colb + k] + bv);
                float v = g_vf[((size_t)b*NPTS + s_idx[colb + k])*CH + ch];
                s += e; a = fmaf(e, v, a);
            }
            o4[p] = a / s;
        }
        size_t base = ((size_t)(b*CH + ch)) * NPTS + (cb >> 4) + half*4;
        float4 r4 = *(const float4*)(g_nf + base);
        *(float4*)(g_o + base) = make_float4(o4[0]+r4.x, o4[1]+r4.y,
                                             o4[2]+r4.z, o4[3]+r4.w);
    } else {
        // att_pre = M*X1 + cb + aq[pt] - ak[idx], + statsA
        float lsum = 0.f, lsq = 0.f;
        #pragma unroll 4
        for (int i = 0; i < 64; i++) {
            int col = i*2 + (tid >> 7);
            float v = Ws[ch*129 + col] + bv;
            int pt = (cb + col) >> 4;
            v += g_q [((size_t)b*NPTS + pt)         *CH + ch]
               - g_kf[((size_t)b*NPTS + s_idx[col]) *CH + ch];
            lsum += v; lsq = fmaf(v, v, lsq);
            Out[((size_t)b*NK + cb + col)*CH + ch] = v;
        }
        atomicAdd(&s_red[ch >> 4], lsum);
        atomicAdd(&s_red[8 + (ch >> 4)], lsq);
        __syncthreads();
        if (tid < 8) {
            atomicAdd(&g_statsA[b][tid][0], (double)s_red[tid]);
            atomicAdd(&g_statsA[b][tid][1], (double)s_red[8 + tid]);
        }
    }
}

// ---------------- post GEMM kernel (64 cols, occ 2, + statsP) ----------------
#define POST_SMEM ((128*TS + 128*XT2 + 16) * 4)
__global__ __launch_bounds__(256, 2) void post_kernel(
        const float* __restrict__ W, const float* __restrict__ bias) {
    const int b  = blockIdx.y;
    const int n0 = blockIdx.x * 64;
    extern __shared__ float sm[];
    float* Ws = sm;
    float* Xs = sm + 128 * TS;
    float* s_red = sm + 128 * TS + 128 * XT2;
    const int tid = threadIdx.x;
    if (tid < 16) s_red[tid] = 0.f;
    for (int e = tid; e < CH * 128; e += 256) {
        int m = e >> 7, k = e & 127;
        Ws[k * TS + m] = W[e];
    }
    const float* Xp = g_o + (size_t)b * CH * NPTS + n0;
    for (int e = tid; e < 128 * 64; e += 256) {
        int k = e >> 6, c = e & 63;
        Xs[k * XT2 + c] = Xp[(size_t)k * NPTS + c];
    }
    __syncthreads();
    const int ty = tid >> 4, tx = tid & 15;
    float acc[8][4];
    #pragma unroll
    for (int i = 0; i < 8; i++)
        #pragma unroll
        for (int j = 0; j < 4; j++) acc[i][j] = 0.f;
    #pragma unroll 4
    for (int k = 0; k < 128; k++) {
        float4 w0 = *(const float4*)(Ws + k*TS + ty*8);
        float4 w1 = *(const float4*)(Ws + k*TS + ty*8 + 4);
        float4 x0 = *(const float4*)(Xs + k*XT2 + tx*4);
        float wf[8] = {w0.x,w0.y,w0.z,w0.w,w1.x,w1.y,w1.z,w1.w};
        float xf[4] = {x0.x,x0.y,x0.z,x0.w};
        #pragma unroll
        for (int i = 0; i < 8; i++)
            #pragma unroll
            for (int j = 0; j < 4; j++)
                acc[i][j] = fmaf(wf[i], xf[j], acc[i][j]);
    }
    float lsum = 0.f, lsq = 0.f;
    #pragma unroll
    for (int i = 0; i < 8; i++) {
        int r = ty*8 + i;
        float bf = bias[r];
        float* yp = g_y + ((size_t)b * CH + r) * NPTS + n0 + tx*4;
        float o[4];
        #pragma unroll
        for (int j = 0; j < 4; j++) {
            o[j] = acc[i][j] + bf;
            lsum += o[j]; lsq = fmaf(o[j], o[j], lsq);
        }
        *(float4*)yp = make_float4(o[0], o[1], o[2], o[3]);
    }
    atomicAdd(&s_red[ty >> 1], lsum);
    atomicAdd(&s_red[8 + (ty >> 1)], lsq);
    __syncthreads();
    if (tid < 8) {
        atomicAdd(&g_statsP[b][tid][0], (double)s_red[tid]);
        atomicAdd(&g_statsP[b][tid][1], (double)s_red[8 + tid]);
    }
}

// ---------------- pass4 ------------------------------------------------------
__global__ __launch_bounds__(256) void pass4_kernel(
        const float* __restrict__ post_g, const float* __restrict__ post_be,
        float* __restrict__ out) {
    int i = blockIdx.x * 256 + threadIdx.x;
    int c = (i / NPTS) & 127;
    int b = i / (CH * NPTS);
    int g = c >> 4;
    double cnt = (double)(CPG * NPTS);
    double su = g_statsP[b][g][0], sq = g_statsP[b][g][1];
    double mean = su / cnt;
    float rstd = (float)(1.0 / sqrt(sq/cnt - mean*mean + 1e-5));
    float v = g_y[i];
    v = fmaf((v - (float)mean) * rstd, post_g[c], post_be[c]);
    out[i] = v >= 0.f ? v : 0.1f*v;
}

// ---------------- launcher ---------------------------------------------------
extern "C" void kernel_launch(void* const* d_in, const int* in_sizes, int n_in,
                              void* d_out, int out_size) {
    const float* xyz    = (const float*)d_in[0];
    const float* feat   = (const float*)d_in[1];
    const float* pre_w  = (const float*)d_in[2];
    const float* pre_b  = (const float*)d_in[3];
    const float* wq_w   = (const float*)d_in[4];
    const float* wq_b   = (const float*)d_in[5];
    const float* wk_w   = (const float*)d_in[6];
    const float* wk_b   = (const float*)d_in[7];
    const float* wv_w   = (const float*)d_in[8];
    const float* wv_b   = (const float*)d_in[9];
    const float* pos1_w = (const float*)d_in[10];
    const float* pos1_b = (const float*)d_in[11];
    const float* pos1_g = (const float*)d_in[12];
    const float* pos1_be= (const float*)d_in[13];
    const float* pos2_w = (const float*)d_in[14];
    const float* pos2_b = (const float*)d_in[15];
    const float* att1_w = (const float*)d_in[16];
    const float* att1_b = (const float*)d_in[17];
    const float* att1_g = (const float*)d_in[18];
    const float* att1_be= (const float*)d_in[19];
    const float* att2_w = (const float*)d_in[20];
    const float* att2_b = (const float*)d_in[21];
    const float* post_w = (const float*)d_in[22];
    const float* post_b = (const float*)d_in[23];
    const float* post_g = (const float*)d_in[24];
    const float* post_be= (const float*)d_in[25];
    float* out = (float*)d_out;

    void* p;
    cudaGetSymbolAddress(&p, g_wt);   float* wt   = (float*)p;
    cudaGetSymbolAddress(&p, g_bufA); float* bufA = (float*)p;
    cudaGetSymbolAddress(&p, g_wqc);  float* wqc  = (float*)p;
    cudaGetSymbolAddress(&p, g_wkc);  float* wkc  = (float*)p;
    cudaGetSymbolAddress(&p, g_cb);   float* cbp  = (float*)p;
    cudaGetSymbolAddress(&p, g_bqc);  float* bqc  = (float*)p;
    cudaGetSymbolAddress(&p, g_bkc);  float* bkc  = (float*)p;

    const int smPre  = (64 + 64) * TS * 4;
    cudaFuncSetAttribute(pre_kernel,   cudaFuncAttributeMaxDynamicSharedMemorySize, smPre);
    cudaFuncSetAttribute(qkv_kernel,   cudaFuncAttributeMaxDynamicSharedMemorySize, QKV_SMEM);
    cudaFuncSetAttribute(post_kernel,  cudaFuncAttributeMaxDynamicSharedMemorySize, POST_SMEM);
    cudaFuncSetAttribute(bgemm_kernel<1>, cudaFuncAttributeMaxDynamicSharedMemorySize, BG_SMEM);
    cudaFuncSetAttribute(bgemm_kernel<3>, cudaFuncAttributeMaxDynamicSharedMemorySize, BG_SMEM);

    compose_kernel<<<dim3(64, 3), 256>>>(att1_w, pos2_w, wq_w, wk_w);
    prep2_kernel<<<32, 512>>>(att2_w, att1_w, pos2_b, att1_b, wq_b, wk_b);
    knn_kernel<<<dim3(NPTS/128, NB), 128>>>(xyz);
    pre_kernel<<<dim3(NPTS/128, NB), 256, smPre>>>(pre_w, pre_b, feat);
    qkv_kernel<<<dim3(NPTS/64, NB, 3), 256, QKV_SMEM>>>(wqc, bqc, wkc, bkc, wv_w, wv_b);
    bgemm_kernel<1><<<dim3(NK/128, NB), 256, BG_SMEM>>>(wt,         cbp, nullptr, bufA,
                                                        pos1_g, pos1_be, xyz, pos1_w, pos1_b);
    bgemm_kernel<3><<<dim3(NK/128, NB), 256, BG_SMEM>>>(wt + 16384, att2_b, bufA, nullptr,
                                                        att1_g, att1_be, nullptr, nullptr, nullptr);
    post_kernel<<<dim3(NPTS/64, NB), 256, POST_SMEM>>>(post_w, post_b);
    pass4_kernel<<<(NB*CH*NPTS)/256, 256>>>(post_g, post_be, out);
    zero_stats_kernel<<<1, 64>>>();
}

// round 16
// speedup vs baseline: 1.5969x; 1.5969x over previous
#include <cuda_runtime.h>
#include <cstdint>

#define NB 2
#define NPTS 8192
#define CH 128
#define KNN 16
#define NGRP 8
#define CPG 16
#define NK (NPTS*KNN)
#define TS 132          /* pre SIMT gemm f32 stride */
#define WST 132         /* bgemm W smem stride */
#define XT2 68          /* qkv/post X tile stride */
typedef unsigned long long u64;

// ---------------- scratch ----------------------------------------------------
__device__ float  g_nf [NB*CH*NPTS];                 // (B,C,N)
__device__ float  g_q  [NB*NPTS*CH];                 // (B,N,C)  aq = att1*q
__device__ float  g_kf [NB*NPTS*CH];                 // (B,N,C)  ak = att1*k
__device__ float  g_vf [NB*NPTS*CH];                 // (B,N,C)  v
__device__ int    g_idx[NB*NPTS*KNN];                // (B,N,K) == (B,NK)
__device__ float  g_bufA[(size_t)NB*NK*CH];          // (B,NK,C) att_pre
__device__ float  g_o  [NB*CH*NPTS];                 // (B,C,N) softmaxV + residual
__device__ float  g_y  [NB*CH*NPTS];                 // (B,C,N) pre-norm post out
__device__ float  g_wt [2*16384];                    // k-major: [0]=M, [1]=att2
__device__ float  g_wqc[16384];                      // row-major att1*wq
__device__ float  g_wkc[16384];                      // row-major att1*wk
__device__ float  g_cb [128];                        // att1*pos2_b + att1_b
__device__ float  g_bqc[128];                        // att1*wq_b
__device__ float  g_bkc[128];                        // att1*wk_b
__device__ double g_relmom[NB][9];                   // zero-init; re-zeroed at end
__device__ double g_statsA[NB][NGRP][2];
__device__ double g_statsP[NB][NGRP][2];

__global__ void zero_stats_kernel() {
    int t = threadIdx.x;
    if (t < NB*9)        ((double*)g_relmom)[t] = 0.0;
    if (t < NB*NGRP*2) { ((double*)g_statsA)[t] = 0.0; ((double*)g_statsP)[t] = 0.0; }
}

// ---------------- weight composition -----------------------------------------
__global__ __launch_bounds__(256) void compose_kernel(
        const float* __restrict__ att1_w, const float* __restrict__ pos2_w,
        const float* __restrict__ wq_w,  const float* __restrict__ wk_w) {
    const int z = blockIdx.y;
    int e = blockIdx.x * 256 + threadIdx.x;     // 16384 per z
    int i = e >> 7, j = e & 127;
    const float* B = (z == 0) ? pos2_w : (z == 1) ? wq_w : wk_w;
    const float* arow = att1_w + i * 128;
    float s = 0.f;
    #pragma unroll 4
    for (int c = 0; c < 128; c++) s = fmaf(__ldg(arow + c), __ldg(B + c*128 + j), s);
    if (z == 0) g_wt[j*128 + i] = s;
    else if (z == 1) g_wqc[e] = s;
    else g_wkc[e] = s;
}
__global__ __launch_bounds__(512) void prep2_kernel(
        const float* __restrict__ att2_w, const float* __restrict__ att1_w,
        const float* __restrict__ pos2_b, const float* __restrict__ att1_b,
        const float* __restrict__ wq_b,  const float* __restrict__ wk_b) {
    int tid = blockIdx.x * 512 + threadIdx.x;
    if (tid < 16384) {
        int o = tid >> 7, k = tid & 127;
        g_wt[16384 + k*128 + o] = att2_w[tid];
    }
    if (blockIdx.x == 0 && threadIdx.x < 384) {
        int z = threadIdx.x >> 7, i = threadIdx.x & 127;
        const float* bb = (z == 0) ? pos2_b : (z == 1) ? wq_b : wk_b;
        const float* arow = att1_w + i * 128;
        float s = 0.f;
        #pragma unroll 4
        for (int c = 0; c < 128; c++) s = fmaf(arow[c], bb[c], s);
        if (z == 0) g_cb[i] = s + att1_b[i];
        else if (z == 1) g_bqc[i] = s;
        else g_bkc[i] = s;
    }
}

// ---------------- f32x2 helpers ----------------------------------------------
__device__ __forceinline__ u64 pack2s(float x) {
    u64 r; asm("mov.b64 %0, {%1,%2};" : "=l"(r) : "f"(x), "f"(x)); return r;
}
__device__ __forceinline__ u64 ffma2(u64 a, u64 b, u64 c) {
    u64 d; asm("fma.rn.f32x2 %0, %1, %2, %3;" : "=l"(d) : "l"(a), "l"(b), "l"(c));
    return d;
}
__device__ __forceinline__ float2 unpk(u64 v) {
    float2 f; asm("mov.b64 {%0,%1}, %2;" : "=f"(f.x), "=f"(f.y) : "l"(v)); return f;
}
__device__ __forceinline__ float warp_sum(float v) {
    #pragma unroll
    for (int o = 16; o > 0; o >>= 1) v += __shfl_down_sync(0xffffffffu, v, o);
    return v;
}

// ---------------- KNN + rel moments ------------------------------------------
__global__ __launch_bounds__(128) void knn_kernel(const float* __restrict__ xyz) {
    const int b = blockIdx.y;
    const int q = blockIdx.x * 128 + threadIdx.x;
    const float* X = xyz + b * 3 * NPTS;
    const float qx = X[q], qy = X[q + NPTS], qz = X[q + 2*NPTS];
    const float c0 = -2.f*qx, c1 = -2.f*qy, c2 = -2.f*qz;
    float nd[KNN]; int ni[KNN];
    #pragma unroll
    for (int i = 0; i < KNN; i++) { nd[i] = 3.4e38f; ni[i] = 0; }
    float worst = 3.4e38f;
    __shared__ float4 tile[256];
    for (int t0 = 0; t0 < NPTS; t0 += 256) {
        __syncthreads();
        for (int j = threadIdx.x; j < 256; j += 128) {
            int jj = t0 + j;
            float x = X[jj], y = X[jj + NPTS], z = X[jj + 2*NPTS];
            tile[j] = make_float4(x, y, z, x*x + y*y + z*z);
        }
        __syncthreads();
        #pragma unroll 4
        for (int j = 0; j < 256; j++) {
            float4 c = tile[j];
            float d = fmaf(c0, c.x, fmaf(c1, c.y, fmaf(c2, c.z, c.w)));
            if (d < worst) {
                int pos = 15;
                #pragma unroll 1
                while (pos > 0 && nd[pos-1] > d) {
                    nd[pos] = nd[pos-1]; ni[pos] = ni[pos-1]; --pos;
                }
                nd[pos] = d; ni[pos] = t0 + j;
                worst = nd[15];
            }
        }
    }
    const int base = (b * NPTS + q) * KNN;
    float mom[9];
    #pragma unroll
    for (int m = 0; m < 9; m++) mom[m] = 0.f;
    #pragma unroll
    for (int i = 0; i < KNN; i++) {
        int j = ni[i];
        g_idx[base + i] = j;
        float dx = X[j] - qx, dy = X[j + NPTS] - qy, dz = X[j + 2*NPTS] - qz;
        mom[0] += dx; mom[1] += dy; mom[2] += dz;
        mom[3] += dx*dx; mom[4] += dx*dy; mom[5] += dx*dz;
        mom[6] += dy*dy; mom[7] += dy*dz; mom[8] += dz*dz;
    }
    int lane = threadIdx.x & 31;
    #pragma unroll
    for (int m = 0; m < 9; m++) {
        float s = warp_sum(mom[m]);
        if (lane == 0) atomicAdd(&g_relmom[b][m], (double)s);
    }
}

// ---------------- SIMT GEMM: pre (Cin=64), occ 2 ------------------------------
__global__ __launch_bounds__(256, 2) void pre_kernel(
        const float* __restrict__ W, const float* __restrict__ bias,
        const float* __restrict__ Xin) {
    const int b  = blockIdx.y;
    const int n0 = blockIdx.x * 128;
    extern __shared__ float sm[];
    float* Ws = sm;
    float* Xs = sm + 64 * TS;
    const int tid = threadIdx.x;
    for (int e = tid; e < CH * 64; e += 256) {
        int m = e >> 6, k = e & 63;
        Ws[k * TS + m] = W[e];
    }
    const float* Xp = Xin + (size_t)b * 64 * NPTS + n0;
    for (int e = tid; e < 64 * 128; e += 256) {
        int k = e >> 7, c = e & 127;
        Xs[k * TS + c] = Xp[(size_t)k * NPTS + c];
    }
    __syncthreads();
    const int ty = tid >> 4, tx = tid & 15;
    float acc[8][8];
    #pragma unroll
    for (int i = 0; i < 8; i++)
        #pragma unroll
        for (int j = 0; j < 8; j++) acc[i][j] = 0.f;
    #pragma unroll 2
    for (int k = 0; k < 64; k++) {
        float4 w0 = *(const float4*)(Ws + k*TS + ty*8);
        float4 w1 = *(const float4*)(Ws + k*TS + ty*8 + 4);
        float4 x0 = *(const float4*)(Xs + k*TS + tx*8);
        float4 x1 = *(const float4*)(Xs + k*TS + tx*8 + 4);
        float wf[8] = {w0.x,w0.y,w0.z,w0.w,w1.x,w1.y,w1.z,w1.w};
        float xf[8] = {x0.x,x0.y,x0.z,x0.w,x1.x,x1.y,x1.z,x1.w};
        #pragma unroll
        for (int i = 0; i < 8; i++)
            #pragma unroll
            for (int j = 0; j < 8; j++)
                acc[i][j] = fmaf(wf[i], xf[j], acc[i][j]);
    }
    #pragma unroll
    for (int i = 0; i < 8; i++) {
        int r = ty*8 + i;
        float bf = bias[r];
        float* yp = g_nf + ((size_t)b * CH + r) * NPTS + n0 + tx*8;
        float4 o0 = {acc[i][0]+bf, acc[i][1]+bf, acc[i][2]+bf, acc[i][3]+bf};
        float4 o1 = {acc[i][4]+bf, acc[i][5]+bf, acc[i][6]+bf, acc[i][7]+bf};
        *(float4*)yp = o0; *(float4*)(yp+4) = o1;
    }
}

// ---------------- fused aq/ak/v GEMM (64 cols, occ 2) -------------------------
#define QKV_SMEM ((128*TS + 128*XT2) * 4)
__global__ __launch_bounds__(256, 2) void qkv_kernel(
        const float* __restrict__ wq, const float* __restrict__ bq,
        const float* __restrict__ wk, const float* __restrict__ bk,
        const float* __restrict__ wv, const float* __restrict__ bv) {
    const int b  = blockIdx.y;
    const int n0 = blockIdx.x * 64;
    const int z  = blockIdx.z;
    const float* W    = (z == 0) ? wq : (z == 1) ? wk : wv;
    const float* bias = (z == 0) ? bq : (z == 1) ? bk : bv;
    float* Y = (z == 0) ? g_q : (z == 1) ? g_kf : g_vf;
    extern __shared__ float sm[];
    float* Ws = sm;
    float* Xs = sm + 128 * TS;
    const int tid = threadIdx.x;
    for (int e = tid; e < CH * 128; e += 256) {
        int m = e >> 7, k = e & 127;
        Ws[k * TS + m] = W[e];
    }
    const float* Xp = g_nf + (size_t)b * CH * NPTS + n0;
    for (int e = tid; e < 128 * 64; e += 256) {
        int k = e >> 6, c = e & 63;
        Xs[k * XT2 + c] = Xp[(size_t)k * NPTS + c];
    }
    __syncthreads();
    const int ty = tid >> 4, tx = tid & 15;
    float acc[8][4];
    #pragma unroll
    for (int i = 0; i < 8; i++)
        #pragma unroll
        for (int j = 0; j < 4; j++) acc[i][j] = 0.f;
    #pragma unroll 4
    for (int k = 0; k < 128; k++) {
        float4 w0 = *(const float4*)(Ws + k*TS + ty*8);
        float4 w1 = *(const float4*)(Ws + k*TS + ty*8 + 4);
        float4 x0 = *(const float4*)(Xs + k*XT2 + tx*4);
        float wf[8] = {w0.x,w0.y,w0.z,w0.w,w1.x,w1.y,w1.z,w1.w};
        float xf[4] = {x0.x,x0.y,x0.z,x0.w};
        #pragma unroll
        for (int i = 0; i < 8; i++)
            #pragma unroll
            for (int j = 0; j < 4; j++)
                acc[i][j] = fmaf(wf[i], xf[j], acc[i][j]);
    }
    float bf[8];
    #pragma unroll
    for (int i = 0; i < 8; i++) bf[i] = bias[ty*8 + i];
    #pragma unroll
    for (int j = 0; j < 4; j++) {
        int c = n0 + tx*4 + j;
        float* yp = Y + ((size_t)b * NPTS + c) * CH + ty*8;
        float4 o0 = {acc[0][j]+bf[0], acc[1][j]+bf[1], acc[2][j]+bf[2], acc[3][j]+bf[3]};
        float4 o1 = {acc[4][j]+bf[4], acc[5][j]+bf[5], acc[6][j]+bf[6], acc[7][j]+bf[7]};
        *(float4*)yp = o0; *(float4*)(yp+4) = o1;
    }
}

// ---------------- statsA reduction over bufA ----------------------------------
__global__ __launch_bounds__(256) void statsA_kernel() {
    const int b  = blockIdx.y;
    const int cb = blockIdx.x * 128;
    __shared__ float s_red[16];
    const int tid = threadIdx.x;
    if (tid < 16) s_red[tid] = 0.f;
    __syncthreads();
    const int ch = tid & 127;
    float lsum = 0.f, lsq = 0.f;
    #pragma unroll 4
    for (int i = 0; i < 64; i++) {
        int col = i*2 + (tid >> 7);
        float v = g_bufA[((size_t)b*NK + cb + col)*CH + ch];
        lsum += v; lsq = fmaf(v, v, lsq);
    }
    atomicAdd(&s_red[ch >> 4], lsum);
    atomicAdd(&s_red[8 + (ch >> 4)], lsq);
    __syncthreads();
    if (tid < 8) {
        atomicAdd(&g_statsA[b][tid][0], (double)s_red[tid]);
        atomicAdd(&g_statsA[b][tid][1], (double)s_red[8 + tid]);
    }
}

// ---------------- big streaming GEMM -----------------------------------------
// MODE 1: X generated from rel (pos1+GN+lrelu); out = M*X1 + cb + aq - ak -> bufA
// MODE 3: X gn+lrelu on load; epilogue = softmax*V + residual -> g_o
#define BG_SMEM ((128*WST + 2*16*WST + 1536) * 4)
template<int MODE>
__global__ __launch_bounds__(256, 2) void bgemm_kernel(
        const float* __restrict__ Wg, const float* __restrict__ bias,
        const float* __restrict__ Xin, float* __restrict__ Out,
        const float* __restrict__ gnw, const float* __restrict__ gnb,
        const float* __restrict__ xyz,
        const float* __restrict__ p1w, const float* __restrict__ p1b) {
    const int b  = blockIdx.y;
    const int cb = blockIdx.x * 128;
    extern __shared__ float sm[];
    float* Ws   = sm;                       // [128][WST]; later C staging [ch][129]
    float* Xb0  = sm + 128*WST;             // [16][WST]
    float* Xb1  = Xb0 + 16*WST;
    float* misc = Xb1 + 16*WST;
    float* s_bias = misc;                   // 128
    int*   s_idx  = (int*)(misc + 128);     // 128
    float* s_m    = misc + 256;             // 8
    float* s_r    = misc + 264;             // 8
    float* s_wA   = misc + 288;             // 384 (MODE1)
    float* s_c0   = misc + 672;             // 128 (MODE1)
    float* s_rx   = misc + 800;             // 128 (MODE1)
    float* s_ry   = misc + 928;             // 128
    float* s_rz   = misc + 1056;            // 128
    float* s_ga   = misc + 1184;            // 128 (MODE3)
    float* s_be   = misc + 1312;            // 128 (MODE3)
    const int tid = threadIdx.x;
    const int lane = tid & 31;
    const int r0 = (tid >> 5) * 16;
    const int c0 = lane * 2;

    if (tid < 128) s_bias[tid] = bias[tid];
    if (tid < 128) s_idx[tid] = g_idx[b*NK + cb + tid];
    if (MODE == 1) {
        if (tid < 128) {
            const float* X = xyz + b * 3 * NPTS;
            int j = g_idx[b*NK + cb + tid];
            int n = (cb >> 4) + (tid >> 4);
            s_rx[tid] = X[j]          - X[n];
            s_ry[tid] = X[j + NPTS]   - X[n + NPTS];
            s_rz[tid] = X[j + 2*NPTS] - X[n + 2*NPTS];
        }
        if (tid < 8) {   // closed-form pos1 GN stats from rel moments
            double R0 = g_relmom[b][0], R1 = g_relmom[b][1], R2 = g_relmom[b][2];
            double S00 = g_relmom[b][3], S01 = g_relmom[b][4], S02 = g_relmom[b][5];
            double S11 = g_relmom[b][6], S12 = g_relmom[b][7], S22 = g_relmom[b][8];
            double su = 0.0, sq = 0.0;
            for (int o = tid*16; o < tid*16 + 16; o++) {
                double w0 = p1w[o*3], w1 = p1w[o*3+1], w2 = p1w[o*3+2];
                double bb = p1b[o];
                double wr = w0*R0 + w1*R1 + w2*R2;
                su += wr + (double)NK * bb;
                double wsw = w0*w0*S00 + w1*w1*S11 + w2*w2*S22
                           + 2.0*(w0*w1*S01 + w0*w2*S02 + w1*w2*S12);
                sq += wsw + 2.0*bb*wr + (double)NK*bb*bb;
            }
            double cnt  = 16.0 * (double)NK;
            double mean = su / cnt;
            double var  = sq / cnt - mean*mean;
            s_m[tid] = (float)mean;
            s_r[tid] = (float)(1.0 / sqrt(var + 1e-5));
        }
    }
    if (MODE == 3) {
        if (tid < 128) { s_ga[tid] = gnw[tid]; s_be[tid] = gnb[tid]; }
        if (tid < 8) {
            double cnt = (double)CPG * (double)NK;
            double su = g_statsA[b][tid][0], sq = g_statsA[b][tid][1];
            double mean = su / cnt;
            double var  = sq / cnt - mean*mean;
            s_m[tid] = (float)mean;
            s_r[tid] = (float)(1.0 / sqrt(var + 1e-5));
        }
    }
    // W -> smem k-major
    for (int e = tid; e < 16384; e += 256) Ws[(e >> 7)*WST + (e & 127)] = Wg[e];
    if (MODE == 1) {
        __syncthreads();     // stats ready
        if (tid < 128) {     // folded GN constants
            float sc = s_r[tid >> 4] * gnw[tid];
            s_wA[tid*3+0] = p1w[tid*3+0] * sc;
            s_wA[tid*3+1] = p1w[tid*3+1] * sc;
            s_wA[tid*3+2] = p1w[tid*3+2] * sc;
            s_c0[tid] = (p1b[tid] - s_m[tid >> 4]) * sc + gnb[tid];
        }
    }
    __syncthreads();

    const int lcol = tid >> 1, lseg = tid & 1;
    const float* xsrc = (MODE == 1) ? nullptr
                      : Xin + ((size_t)b*NK + cb + lcol)*CH + lseg*8;
    const float rx = (MODE == 1) ? s_rx[lcol] : 0.f;
    const float ry = (MODE == 1) ? s_ry[lcol] : 0.f;
    const float rz = (MODE == 1) ? s_rz[lcol] : 0.f;

    // produce chunk 0
    {
        float v8[8];
        #pragma unroll
        for (int i = 0; i < 8; i++) {
            if (MODE == 1) {
                int ch = lseg*8 + i;
                float t = fmaf(s_wA[ch*3], rx, fmaf(s_wA[ch*3+1], ry,
                          fmaf(s_wA[ch*3+2], rz, s_c0[ch])));
                v8[i] = t >= 0.f ? t : 0.1f*t;
            }
        }
        if (MODE != 1) {
            float4 pa = *(const float4*)(xsrc);
            float4 pb = *(const float4*)(xsrc + 4);
            #pragma unroll
            for (int i = 0; i < 8; i++)
                v8[i] = (i < 4) ? (&pa.x)[i] : (&pb.x)[i-4];
            #pragma unroll
            for (int i = 0; i < 8; i++) {
                int ch = lseg*8 + i;
                float t = fmaf((v8[i] - s_m[ch>>4]) * s_r[ch>>4], s_ga[ch], s_be[ch]);
                v8[i] = t >= 0.f ? t : 0.1f*t;
            }
        }
        #pragma unroll
        for (int i = 0; i < 8; i++) Xb0[(lseg*8+i)*WST + lcol] = v8[i];
    }
    __syncthreads();

    u64 acc[8][4];
    #pragma unroll
    for (int m = 0; m < 8; m++)
        #pragma unroll
        for (int j = 0; j < 4; j++) acc[m][j] = 0ull;

    #pragma unroll 1
    for (int c = 0; c < 8; c++) {
        float v8[8];
        if (c < 7) {
            if (MODE == 1) {
                #pragma unroll
                for (int i = 0; i < 8; i++) {
                    int ch = (c+1)*16 + lseg*8 + i;
                    float t = fmaf(s_wA[ch*3], rx, fmaf(s_wA[ch*3+1], ry,
                              fmaf(s_wA[ch*3+2], rz, s_c0[ch])));
                    v8[i] = t >= 0.f ? t : 0.1f*t;
                }
            } else {
                const float* src = xsrc + (c+1)*16;
                float4 pa = *(const float4*)(src);
                float4 pb = *(const float4*)(src + 4);
                #pragma unroll
                for (int i = 0; i < 8; i++)
                    v8[i] = (i < 4) ? (&pa.x)[i] : (&pb.x)[i-4];
                #pragma unroll
                for (int i = 0; i < 8; i++) {
                    int ch = (c+1)*16 + lseg*8 + i;
                    float t = fmaf((v8[i] - s_m[ch>>4]) * s_r[ch>>4], s_ga[ch], s_be[ch]);
                    v8[i] = t >= 0.f ? t : 0.1f*t;
                }
            }
        }
        const float* Wc = Ws + c*16*WST;
        const float* Xc = (c & 1) ? Xb1 : Xb0;
        #pragma unroll
        for (int kk = 0; kk < 16; kk++) {
            const ulonglong2* wp = (const ulonglong2*)(Wc + kk*WST + r0);
            ulonglong2 wA = wp[0], wB = wp[1], wC = wp[2], wD = wp[3];
            const float* xp = Xc + kk*WST + c0;
            u64 xa = *(const u64*)xp, xbv = *(const u64*)(xp + 64);
            float2 fa = unpk(xa), fb = unpk(xbv);
            u64 x0 = pack2s(fa.x), x1 = pack2s(fa.y);
            u64 x2 = pack2s(fb.x), x3 = pack2s(fb.y);
            acc[0][0]=ffma2(wA.x,x0,acc[0][0]); acc[0][1]=ffma2(wA.x,x1,acc[0][1]);
            acc[0][2]=ffma2(wA.x,x2,acc[0][2]); acc[0][3]=ffma2(wA.x,x3,acc[0][3]);
            acc[1][0]=ffma2(wA.y,x0,acc[1][0]); acc[1][1]=ffma2(wA.y,x1,acc[1][1]);
            acc[1][2]=ffma2(wA.y,x2,acc[1][2]); acc[1][3]=ffma2(wA.y,x3,acc[1][3]);
            acc[2][0]=ffma2(wB.x,x0,acc[2][0]); acc[2][1]=ffma2(wB.x,x1,acc[2][1]);
            acc[2][2]=ffma2(wB.x,x2,acc[2][2]); acc[2][3]=ffma2(wB.x,x3,acc[2][3]);
            acc[3][0]=ffma2(wB.y,x0,acc[3][0]); acc[3][1]=ffma2(wB.y,x1,acc[3][1]);
            acc[3][2]=ffma2(wB.y,x2,acc[3][2]); acc[3][3]=ffma2(wB.y,x3,acc[3][3]);
            acc[4][0]=ffma2(wC.x,x0,acc[4][0]); acc[4][1]=ffma2(wC.x,x1,acc[4][1]);
            acc[4][2]=ffma2(wC.x,x2,acc[4][2]); acc[4][3]=ffma2(wC.x,x3,acc[4][3]);
            acc[5][0]=ffma2(wC.y,x0,acc[5][0]); acc[5][1]=ffma2(wC.y,x1,acc[5][1]);
            acc[5][2]=ffma2(wC.y,x2,acc[5][2]); acc[5][3]=ffma2(wC.y,x3,acc[5][3]);
            acc[6][0]=ffma2(wD.x,x0,acc[6][0]); acc[6][1]=ffma2(wD.x,x1,acc[6][1]);
            acc[6][2]=ffma2(wD.x,x2,acc[6][2]); acc[6][3]=ffma2(wD.x,x3,acc[6][3]);
            acc[7][0]=ffma2(wD.y,x0,acc[7][0]); acc[7][1]=ffma2(wD.y,x1,acc[7][1]);
            acc[7][2]=ffma2(wD.y,x2,acc[7][2]); acc[7][3]=ffma2(wD.y,x3,acc[7][3]);
        }
        if (c < 7) {
            float* Xn = (c & 1) ? Xb0 : Xb1;
            #pragma unroll
            for (int i = 0; i < 8; i++) Xn[(lseg*8+i)*WST + lcol] = v8[i];
        }
        __syncthreads();
    }

    // stage C into Ws region [ch][col] at stride 129 (conflict-free reads)
    #pragma unroll
    for (int mp = 0; mp < 8; mp++) {
        int r = r0 + 2*mp;
        #pragma unroll
        for (int j = 0; j < 4; j++) {
            int col = c0 + (j & 1) + 64*(j >> 1);
            float2 d = unpk(acc[mp][j]);
            Ws[r*129 + col]     = d.x;
            Ws[(r+1)*129 + col] = d.y;
        }
    }
    __syncthreads();

    const int ch = tid & 127;
    const float bv = s_bias[ch];
    if (MODE == 3) {
        // softmax over K=16 per point (block holds 8 complete points) + V + res
        const int half = tid >> 7;
        float o4[4];
        #pragma unroll
        for (int p = 0; p < 4; p++) {
            int colb = (half*4 + p) * 16;
            float s = 0.f, a = 0.f;
            #pragma unroll
            for (int k = 0; k < 16; k++) {
                float e = __expf(Ws[ch*129 + colb + k] + bv);
                float v = g_vf[((size_t)b*NPTS + s_idx[colb + k])*CH + ch];
                s += e; a = fmaf(e, v, a);
            }
            o4[p] = a / s;
        }
        size_t base = ((size_t)(b*CH + ch)) * NPTS + (cb >> 4) + half*4;
        float4 r4 = *(const float4*)(g_nf + base);
        *(float4*)(g_o + base) = make_float4(o4[0]+r4.x, o4[1]+r4.y,
                                             o4[2]+r4.z, o4[3]+r4.w);
    } else {
        // att_pre = M*X1 + cb + aq[pt] - ak[idx]  (stats in separate kernel)
        #pragma unroll 4
        for (int i = 0; i < 64; i++) {
            int col = i*2 + (tid >> 7);
            float v = Ws[ch*129 + col] + bv;
            int pt = (cb + col) >> 4;
            v += g_q [((size_t)b*NPTS + pt)         *CH + ch]
               - g_kf[((size_t)b*NPTS + s_idx[col]) *CH + ch];
            Out[((size_t)b*NK + cb + col)*CH + ch] = v;
        }
    }
}

// ---------------- post GEMM kernel (64 cols, occ 2, + statsP) ----------------
#define POST_SMEM ((128*TS + 128*XT2 + 16) * 4)
__global__ __launch_bounds__(256, 2) void post_kernel(
        const float* __restrict__ W, const float* __restrict__ bias) {
    const int b  = blockIdx.y;
    const int n0 = blockIdx.x * 64;
    extern __shared__ float sm[];
    float* Ws = sm;
    float* Xs = sm + 128 * TS;
    float* s_red = sm + 128 * TS + 128 * XT2;
    const int tid = threadIdx.x;
    if (tid < 16) s_red[tid] = 0.f;
    for (int e = tid; e < CH * 128; e += 256) {
        int m = e >> 7, k = e & 127;
        Ws[k * TS + m] = W[e];
    }
    const float* Xp = g_o + (size_t)b * CH * NPTS + n0;
    for (int e = tid; e < 128 * 64; e += 256) {
        int k = e >> 6, c = e & 63;
        Xs[k * XT2 + c] = Xp[(size_t)k * NPTS + c];
    }
    __syncthreads();
    const int ty = tid >> 4, tx = tid & 15;
    float acc[8][4];
    #pragma unroll
    for (int i = 0; i < 8; i++)
        #pragma unroll
        for (int j = 0; j < 4; j++) acc[i][j] = 0.f;
    #pragma unroll 4
    for (int k = 0; k < 128; k++) {
        float4 w0 = *(const float4*)(Ws + k*TS + ty*8);
        float4 w1 = *(const float4*)(Ws + k*TS + ty*8 + 4);
        float4 x0 = *(const float4*)(Xs + k*XT2 + tx*4);
        float wf[8] = {w0.x,w0.y,w0.z,w0.w,w1.x,w1.y,w1.z,w1.w};
        float xf[4] = {x0.x,x0.y,x0.z,x0.w};
        #pragma unroll
        for (int i = 0; i < 8; i++)
            #pragma unroll
            for (int j = 0; j < 4; j++)
                acc[i][j] = fmaf(wf[i], xf[j], acc[i][j]);
    }
    float lsum = 0.f, lsq = 0.f;
    #pragma unroll
    for (int i = 0; i < 8; i++) {
        int r = ty*8 + i;
        float bf = bias[r];
        float* yp = g_y + ((size_t)b * CH + r) * NPTS + n0 + tx*4;
        float o[4];
        #pragma unroll
        for (int j = 0; j < 4; j++) {
            o[j] = acc[i][j] + bf;
            lsum += o[j]; lsq = fmaf(o[j], o[j], lsq);
        }
        *(float4*)yp = make_float4(o[0], o[1], o[2], o[3]);
    }
    atomicAdd(&s_red[ty >> 1], lsum);
    atomicAdd(&s_red[8 + (ty >> 1)], lsq);
    __syncthreads();
    if (tid < 8) {
        atomicAdd(&g_statsP[b][tid][0], (double)s_red[tid]);
        atomicAdd(&g_statsP[b][tid][1], (double)s_red[8 + tid]);
    }
}

// ---------------- pass4 ------------------------------------------------------
__global__ __launch_bounds__(256) void pass4_kernel(
        const float* __restrict__ post_g, const float* __restrict__ post_be,
        float* __restrict__ out) {
    int i = blockIdx.x * 256 + threadIdx.x;
    int c = (i / NPTS) & 127;
    int b = i / (CH * NPTS);
    int g = c >> 4;
    double cnt = (double)(CPG * NPTS);
    double su = g_statsP[b][g][0], sq = g_statsP[b][g][1];
    double mean = su / cnt;
    float rstd = (float)(1.0 / sqrt(sq/cnt - mean*mean + 1e-5));
    float v = g_y[i];
    v = fmaf((v - (float)mean) * rstd, post_g[c], post_be[c]);
    out[i] = v >= 0.f ? v : 0.1f*v;
}

// ---------------- launcher ---------------------------------------------------
extern "C" void kernel_launch(void* const* d_in, const int* in_sizes, int n_in,
                              void* d_out, int out_size) {
    const float* xyz    = (const float*)d_in[0];
    const float* feat   = (const float*)d_in[1];
    const float* pre_w  = (const float*)d_in[2];
    const float* pre_b  = (const float*)d_in[3];
    const float* wq_w   = (const float*)d_in[4];
    const float* wq_b   = (const float*)d_in[5];
    const float* wk_w   = (const float*)d_in[6];
    const float* wk_b   = (const float*)d_in[7];
    const float* wv_w   = (const float*)d_in[8];
    const float* wv_b   = (const float*)d_in[9];
    const float* pos1_w = (const float*)d_in[10];
    const float* pos1_b = (const float*)d_in[11];
    const float* pos1_g = (const float*)d_in[12];
    const float* pos1_be= (const float*)d_in[13];
    const float* pos2_w = (const float*)d_in[14];
    const float* pos2_b = (const float*)d_in[15];
    const float* att1_w = (const float*)d_in[16];
    const float* att1_b = (const float*)d_in[17];
    const float* att1_g = (const float*)d_in[18];
    const float* att1_be= (const float*)d_in[19];
    const float* att2_w = (const float*)d_in[20];
    const float* att2_b = (const float*)d_in[21];
    const float* post_w = (const float*)d_in[22];
    const float* post_b = (const float*)d_in[23];
    const float* post_g = (const float*)d_in[24];
    const float* post_be= (const float*)d_in[25];
    float* out = (float*)d_out;

    void* p;
    cudaGetSymbolAddress(&p, g_wt);   float* wt   = (float*)p;
    cudaGetSymbolAddress(&p, g_bufA); float* bufA = (float*)p;
    cudaGetSymbolAddress(&p, g_wqc);  float* wqc  = (float*)p;
    cudaGetSymbolAddress(&p, g_wkc);  float* wkc  = (float*)p;
    cudaGetSymbolAddress(&p, g_cb);   float* cbp  = (float*)p;
    cudaGetSymbolAddress(&p, g_bqc);  float* bqc  = (float*)p;
    cudaGetSymbolAddress(&p, g_bkc);  float* bkc  = (float*)p;

    const int smPre  = (64 + 64) * TS * 4;
    cudaFuncSetAttribute(pre_kernel,   cudaFuncAttributeMaxDynamicSharedMemorySize, smPre);
    cudaFuncSetAttribute(qkv_kernel,   cudaFuncAttributeMaxDynamicSharedMemorySize, QKV_SMEM);
    cudaFuncSetAttribute(post_kernel,  cudaFuncAttributeMaxDynamicSharedMemorySize, POST_SMEM);
    cudaFuncSetAttribute(bgemm_kernel<1>, cudaFuncAttributeMaxDynamicSharedMemorySize, BG_SMEM);
    cudaFuncSetAttribute(bgemm_kernel<3>, cudaFuncAttributeMaxDynamicSharedMemorySize, BG_SMEM);

    compose_kernel<<<dim3(64, 3), 256>>>(att1_w, pos2_w, wq_w, wk_w);
    prep2_kernel<<<32, 512>>>(att2_w, att1_w, pos2_b, att1_b, wq_b, wk_b);
    knn_kernel<<<dim3(NPTS/128, NB), 128>>>(xyz);
    pre_kernel<<<dim3(NPTS/128, NB), 256, smPre>>>(pre_w, pre_b, feat);
    qkv_kernel<<<dim3(NPTS/64, NB, 3), 256, QKV_SMEM>>>(wqc, bqc, wkc, bkc, wv_w, wv_b);
    bgemm_kernel<1><<<dim3(NK/128, NB), 256, BG_SMEM>>>(wt,         cbp, nullptr, bufA,
                                                        pos1_g, pos1_be, xyz, pos1_w, pos1_b);
    statsA_kernel<<<dim3(NK/128, NB), 256>>>();
    bgemm_kernel<3><<<dim3(NK/128, NB), 256, BG_SMEM>>>(wt + 16384, att2_b, bufA, nullptr,
                                                        att1_g, att1_be, nullptr, nullptr, nullptr);
    post_kernel<<<dim3(NPTS/64, NB), 256, POST_SMEM>>>(post_w, post_b);
    pass4_kernel<<<(NB*CH*NPTS)/256, 256>>>(post_g, post_be, out);
    zero_stats_kernel<<<1, 64>>>();
}